// round 1
// baseline (speedup 1.0000x reference)
#include <cuda_runtime.h>
#include <math.h>

// ---------------------------------------------------------------------------
// Problem constants
// ---------------------------------------------------------------------------
namespace cfg {
constexpr int Bn  = 8;
constexpr int Cch = 256;
constexpr int Hh  = 112;
constexpr int Ww  = 112;
constexpr int HW  = Hh * Ww;        // 12544
constexpr int Pp  = 196;            // patch_area
constexpr int Ss  = 64;             // split_head_num
constexpr int CS  = Cch * Ss;       // 16384
constexpr int TG  = 56;             // target_global
constexpr int A2  = TG * TG;        // 3136
}
using namespace cfg;

// ---------------------------------------------------------------------------
// Scratch (__device__ globals; no runtime allocation allowed)
// ---------------------------------------------------------------------------
__device__ float  g_qkv [(long long)Bn * 768 * HW];   // stacked q(0..255)/k(256..511)/v(512..767) per batch
__device__ float  g_qkvp[(long long)Bn * 768 * A2];   // pooled q/k/v
__device__ float  g_attp[(long long)Bn * Pp * Pp];    // patch attention logits/probs
__device__ float  g_attg[(long long)Bn * A2 * A2];    // global attention logits/probs (~315 MB)
__device__ float  g_hp  [(long long)Bn * Cch * HW];   // patch attention output
__device__ float  g_hg  [(long long)Bn * Cch * A2];   // global attention output (56x56)
__device__ float  g_h   [(long long)Bn * Cch * HW];   // combined h
__device__ float  g_wp  [(long long)Bn * 768 * 256];  // groupnorm-folded qkv weights per batch
__device__ float  g_bp  [(long long)Bn * 768];        // folded biases
__device__ double g_stats[2 * Bn];                    // per-batch sum / sumsq
__device__ float  g_mu[Bn], g_rstd[Bn];

// ---------------------------------------------------------------------------
// 1) Per-batch GroupNorm statistics (mean / rstd over C*H*W)
// ---------------------------------------------------------------------------
__global__ void stats_kernel(const float* __restrict__ x)
{
    int b = blockIdx.y;
    const float* xb = x + (long long)b * Cch * HW;
    long long n = (long long)Cch * HW;
    double s = 0.0, s2 = 0.0;
    for (long long i = blockIdx.x * (long long)blockDim.x + threadIdx.x; i < n;
         i += (long long)gridDim.x * blockDim.x) {
        double v = xb[i];
        s += v; s2 += v * v;
    }
    __shared__ double rs[256], rs2[256];
    int tid = threadIdx.x;
    rs[tid] = s; rs2[tid] = s2;
    __syncthreads();
    for (int t = 128; t > 0; t >>= 1) {
        if (tid < t) { rs[tid] += rs[tid + t]; rs2[tid] += rs2[tid + t]; }
        __syncthreads();
    }
    if (tid == 0) {
        atomicAdd(&g_stats[2 * b],     rs[0]);
        atomicAdd(&g_stats[2 * b + 1], rs2[0]);
    }
}

__global__ void finalize_stats()
{
    int b = threadIdx.x;
    if (b < Bn) {
        double n    = (double)Cch * HW;
        double mean = g_stats[2 * b] / n;
        double var  = g_stats[2 * b + 1] / n - mean * mean;
        g_mu[b]   = (float)mean;
        g_rstd[b] = (float)(1.0 / sqrt(var + 1e-5));
    }
}

// ---------------------------------------------------------------------------
// 2) Fold GroupNorm into the QKV weights:
//    Q = Wq @ xn + bq  with  xn = diag(gw*rstd)(x - mu) + gb
//    => W'[o,c] = W[o,c]*gw[c]*rstd ;  b'[o] = b[o] + sum_c W[o,c]*(gb[c] - gw[c]*rstd*mu)
// ---------------------------------------------------------------------------
__global__ void prep_weights(const float* __restrict__ wq, const float* __restrict__ bq,
                             const float* __restrict__ wk, const float* __restrict__ bk,
                             const float* __restrict__ wv, const float* __restrict__ bv,
                             const float* __restrict__ gnw, const float* __restrict__ gnb)
{
    int r = blockIdx.x;            // 0..767
    int b = blockIdx.y;
    int mat = r >> 8, o = r & 255;
    const float* W  = (mat == 0) ? wq : (mat == 1) ? wk : wv;
    const float* bi = (mat == 0) ? bq : (mat == 1) ? bk : bv;
    int c = threadIdx.x;           // 256 threads
    float rstd = g_rstd[b], mu = g_mu[b];
    float w = W[o * 256 + c];
    g_wp[((long long)b * 768 + r) * 256 + c] = w * gnw[c] * rstd;
    float contrib = w * (gnb[c] - gnw[c] * rstd * mu);
    __shared__ float red[256];
    red[c] = contrib;
    __syncthreads();
    for (int s = 128; s > 0; s >>= 1) {
        if (c < s) red[c] += red[c + s];
        __syncthreads();
    }
    if (c == 0) g_bp[(long long)b * 768 + r] = red[0] + bi[o];
}

// ---------------------------------------------------------------------------
// Generic batched tiled SGEMM: C[m,n] = sum_k opA(m,k)*opB(k,n)  (+bias[m]) (+resid)
//   TA=false: A is MxK row-major (A[m*lda+k]);  TA=true: A is KxM row-major (A[k*lda+m])
//   TB=false: B is KxN row-major (B[k*ldb+n]);  TB=true: B is NxK row-major (B[n*ldb+k])
//   ksplit > 1: blockIdx.z = batch*ksplit + kchunk, partial sums via atomicAdd (C pre-zeroed)
// 128x128 tile, BK=8, 256 threads, 8x8 per thread.
// ---------------------------------------------------------------------------
template <bool TA, bool TB>
__global__ void __launch_bounds__(256)
sgemm_kernel(const float* __restrict__ A, long long sA, int lda,
             const float* __restrict__ Bm, long long sB, int ldb,
             float* __restrict__ Cm, long long sC, int ldc,
             int M, int N, int K,
             const float* __restrict__ bias, long long sBias,
             const float* __restrict__ resid, long long sRes,
             int ksplit)
{
    int z = blockIdx.z;
    int batch = z / ksplit;
    int kc = z - batch * ksplit;
    int kchunk = (K + ksplit - 1) / ksplit;
    int k0 = kc * kchunk;
    int kEnd = min(K, k0 + kchunk);

    const float* Ab = A  + (long long)batch * sA;
    const float* Bb = Bm + (long long)batch * sB;
    float*       Cb = Cm + (long long)batch * sC;

    int m0 = blockIdx.y * 128;
    int n0 = blockIdx.x * 128;

    __shared__ float As[8][128];
    __shared__ float Bs[8][128];

    int tid = threadIdx.x;
    int tx = tid & 15, ty = tid >> 4;

    float acc[8][8];
#pragma unroll
    for (int i = 0; i < 8; i++)
#pragma unroll
        for (int j = 0; j < 8; j++) acc[i][j] = 0.f;

    for (int kk = k0; kk < kEnd; kk += 8) {
        // ---- load A tile ----
        if (TA) {
            int aK = tid >> 5;            // 0..7
            int aM = (tid & 31) << 2;     // 0..124
            int k = kk + aK;
#pragma unroll
            for (int i = 0; i < 4; i++) {
                int m = m0 + aM + i;
                As[aK][aM + i] = (m < M && k < kEnd) ? Ab[(long long)k * lda + m] : 0.f;
            }
        } else {
            int aR = tid >> 1;            // 0..127
            int aK = (tid & 1) << 2;
            int m = m0 + aR;
#pragma unroll
            for (int i = 0; i < 4; i++) {
                int k = kk + aK + i;
                As[aK + i][aR] = (m < M && k < kEnd) ? Ab[(long long)m * lda + k] : 0.f;
            }
        }
        // ---- load B tile ----
        if (TB) {
            int bR = tid >> 1;            // n index 0..127
            int bK = (tid & 1) << 2;
            int n = n0 + bR;
#pragma unroll
            for (int i = 0; i < 4; i++) {
                int k = kk + bK + i;
                Bs[bK + i][bR] = (n < N && k < kEnd) ? Bb[(long long)n * ldb + k] : 0.f;
            }
        } else {
            int bK = tid >> 5;
            int bN = (tid & 31) << 2;
            int k = kk + bK;
#pragma unroll
            for (int i = 0; i < 4; i++) {
                int n = n0 + bN + i;
                Bs[bK][bN + i] = (n < N && k < kEnd) ? Bb[(long long)k * ldb + n] : 0.f;
            }
        }
        __syncthreads();
#pragma unroll
        for (int k = 0; k < 8; k++) {
            float4 a0 = *(const float4*)&As[k][ty << 2];
            float4 a1 = *(const float4*)&As[k][(ty << 2) + 64];
            float4 b0 = *(const float4*)&Bs[k][tx << 2];
            float4 b1 = *(const float4*)&Bs[k][(tx << 2) + 64];
            float av[8] = {a0.x, a0.y, a0.z, a0.w, a1.x, a1.y, a1.z, a1.w};
            float bv[8] = {b0.x, b0.y, b0.z, b0.w, b1.x, b1.y, b1.z, b1.w};
#pragma unroll
            for (int i = 0; i < 8; i++)
#pragma unroll
                for (int j = 0; j < 8; j++) acc[i][j] += av[i] * bv[j];
        }
        __syncthreads();
    }

    bool doAtomic = (ksplit > 1);
#pragma unroll
    for (int i = 0; i < 8; i++) {
        int m = m0 + ((i < 4) ? (ty << 2) + i : 64 + (ty << 2) + (i - 4));
        if (m >= M) continue;
        float bval = bias ? bias[(long long)batch * sBias + m] : 0.f;
#pragma unroll
        for (int j = 0; j < 8; j++) {
            int n = n0 + ((j < 4) ? (tx << 2) + j : 64 + (tx << 2) + (j - 4));
            if (n >= N) continue;
            long long idx = (long long)m * ldc + n;
            float v = acc[i][j] + bval;
            if (resid) v += resid[(long long)batch * sRes + idx];
            if (doAtomic) atomicAdd(&Cb[idx], v);
            else          Cb[idx] = v;
        }
    }
}

// ---------------------------------------------------------------------------
// 2x2 average pool on the stacked qkv slab: [B,768,112,112] -> [B,768,56,56]
// ---------------------------------------------------------------------------
__global__ void pool_kernel(const float* __restrict__ qkv, float* __restrict__ out)
{
    long long total = (long long)Bn * 768 * A2;
    for (long long idx = blockIdx.x * (long long)blockDim.x + threadIdx.x; idx < total;
         idx += (long long)gridDim.x * blockDim.x) {
        int p = (int)(idx % A2);
        long long br = idx / A2;
        int y = p / TG, x = p % TG;
        const float* src = qkv + br * HW;
        float v = src[(2 * y) * Ww + 2 * x]     + src[(2 * y) * Ww + 2 * x + 1]
                + src[(2 * y + 1) * Ww + 2 * x] + src[(2 * y + 1) * Ww + 2 * x + 1];
        out[idx] = 0.25f * v;
    }
}

// ---------------------------------------------------------------------------
// Row softmax with pre-scale: p[i] = softmax(scale * p[i]) over a row of `len`
// ---------------------------------------------------------------------------
__global__ void softmax_rows(float* __restrict__ data, int len, float scale)
{
    long long row = blockIdx.x;
    float* p = data + row * (long long)len;
    __shared__ float red[256];
    int tid = threadIdx.x;

    float m = -1e30f;
    for (int i = tid; i < len; i += blockDim.x) m = fmaxf(m, p[i] * scale);
    red[tid] = m;
    __syncthreads();
    for (int s = 128; s > 0; s >>= 1) {
        if (tid < s) red[tid] = fmaxf(red[tid], red[tid + s]);
        __syncthreads();
    }
    m = red[0];
    __syncthreads();

    float sum = 0.f;
    for (int i = tid; i < len; i += blockDim.x) sum += expf(p[i] * scale - m);
    red[tid] = sum;
    __syncthreads();
    for (int s = 128; s > 0; s >>= 1) {
        if (tid < s) red[tid] += red[tid + s];
        __syncthreads();
    }
    float inv = 1.f / red[0];
    for (int i = tid; i < len; i += blockDim.x) p[i] = expf(p[i] * scale - m) * inv;
}

// ---------------------------------------------------------------------------
// Combine: h = 0.75*h_patch + 0.25*bilinear_upsample(h_glob, 56->112, half-pixel)
// ---------------------------------------------------------------------------
__global__ void combine_kernel(float* __restrict__ h,
                               const float* __restrict__ hp,
                               const float* __restrict__ hg)
{
    long long total = (long long)Bn * Cch * HW;
    for (long long idx = blockIdx.x * (long long)blockDim.x + threadIdx.x; idx < total;
         idx += (long long)gridDim.x * blockDim.x) {
        int hw = (int)(idx % HW);
        long long bc = idx / HW;
        int i = hw / Ww, j = hw % Ww;
        float sy = 0.5f * i - 0.25f;
        float sx = 0.5f * j - 0.25f;
        int y0 = (int)floorf(sy), x0 = (int)floorf(sx);
        float wy = sy - (float)y0, wx = sx - (float)x0;
        int y0c = min(max(y0, 0), TG - 1), y1c = min(max(y0 + 1, 0), TG - 1);
        int x0c = min(max(x0, 0), TG - 1), x1c = min(max(x0 + 1, 0), TG - 1);
        const float* g = hg + bc * A2;
        float v00 = g[y0c * TG + x0c], v01 = g[y0c * TG + x1c];
        float v10 = g[y1c * TG + x0c], v11 = g[y1c * TG + x1c];
        float gv = (1.f - wy) * ((1.f - wx) * v00 + wx * v01)
                 +        wy  * ((1.f - wx) * v10 + wx * v11);
        h[idx] = 0.75f * hp[idx] + 0.25f * gv;
    }
}

// ---------------------------------------------------------------------------
// Launch
// ---------------------------------------------------------------------------
static inline int cdiv(int a, int b) { return (a + b - 1) / b; }

extern "C" void kernel_launch(void* const* d_in, const int* in_sizes, int n_in,
                              void* d_out, int out_size)
{
    const float* x     = (const float*)d_in[0];
    const float* gnw   = (const float*)d_in[1];
    const float* gnb   = (const float*)d_in[2];
    const float* wq    = (const float*)d_in[3];
    const float* bq    = (const float*)d_in[4];
    const float* wk    = (const float*)d_in[5];
    const float* bk    = (const float*)d_in[6];
    const float* wv    = (const float*)d_in[7];
    const float* bv    = (const float*)d_in[8];
    const float* wproj = (const float*)d_in[9];
    float* out = (float*)d_out;

    void *p_qkv, *p_qkvp, *p_attp, *p_attg, *p_hp, *p_hg, *p_h, *p_wp, *p_bp, *p_stats;
    cudaGetSymbolAddress(&p_qkv,  g_qkv);
    cudaGetSymbolAddress(&p_qkvp, g_qkvp);
    cudaGetSymbolAddress(&p_attp, g_attp);
    cudaGetSymbolAddress(&p_attg, g_attg);
    cudaGetSymbolAddress(&p_hp,   g_hp);
    cudaGetSymbolAddress(&p_hg,   g_hg);
    cudaGetSymbolAddress(&p_h,    g_h);
    cudaGetSymbolAddress(&p_wp,   g_wp);
    cudaGetSymbolAddress(&p_bp,   g_bp);
    cudaGetSymbolAddress(&p_stats, g_stats);

    const float* qkv  = (const float*)p_qkv;
    const float* qkvp = (const float*)p_qkvp;

    // 1) GroupNorm stats
    cudaMemsetAsync(p_stats, 0, 2 * Bn * sizeof(double));
    stats_kernel<<<dim3(128, Bn), 256>>>(x);
    finalize_stats<<<1, Bn>>>();

    // 2) fold GN into qkv weights
    prep_weights<<<dim3(768, Bn), 256>>>(wq, bq, wk, bk, wv, bv, gnw, gnb);

    // 3) QKV GEMM: [768,256] @ [256,12544] per batch (+bias), writes stacked slab
    sgemm_kernel<false, false><<<dim3(cdiv(HW, 128), cdiv(768, 128), Bn), 256>>>(
        (const float*)p_wp, 768LL * 256, 256,
        x, (long long)Cch * HW, HW,
        (float*)p_qkv, 768LL * HW, HW,
        768, HW, 256,
        (const float*)p_bp, 768,
        nullptr, 0, 1);

    // 4) 2x2 average pool of q/k/v
    pool_kernel<<<8192, 256>>>(qkv, (float*)p_qkvp);

    // 5) patch attention logits: att[p,q] = sum_d q[d,p] k[d,q]  (K=16384, split-K=32)
    cudaMemsetAsync(p_attp, 0, (long long)Bn * Pp * Pp * sizeof(float));
    sgemm_kernel<true, false><<<dim3(cdiv(Pp, 128), cdiv(Pp, 128), Bn * 32), 256>>>(
        qkv,                 768LL * HW, Pp,   // A = q (KxM, lda=196)
        qkv + 256LL * HW,    768LL * HW, Pp,   // B = k (KxN)
        (float*)p_attp, (long long)Pp * Pp, Pp,
        Pp, Pp, CS,
        nullptr, 0, nullptr, 0, 32);

    // 6) patch softmax (scale = (C*S)^-0.5 = 1/128)
    softmax_rows<<<Bn * Pp, 256>>>((float*)p_attp, Pp, 1.f / 128.f);

    // 7) patch output: h[d,q] = sum_p v[d,p] att[q,p]
    sgemm_kernel<false, true><<<dim3(cdiv(Pp, 128), cdiv(CS, 128), Bn), 256>>>(
        qkv + 512LL * HW,    768LL * HW, Pp,        // A = v (MxK, lda=196)
        (const float*)p_attp, (long long)Pp * Pp, Pp, // B = att (NxK -> transB)
        (float*)p_hp, (long long)Cch * HW, Pp,
        CS, Pp, Pp,
        nullptr, 0, nullptr, 0, 1);

    // 8) global attention logits: att[p,q] = sum_c qp[c,p] kp[c,q]
    sgemm_kernel<true, false><<<dim3(cdiv(A2, 128), cdiv(A2, 128), Bn), 256>>>(
        qkvp,                768LL * A2, A2,    // A = qp (KxM, lda=3136)
        qkvp + 256LL * A2,   768LL * A2, A2,    // B = kp
        (float*)p_attg, (long long)A2 * A2, A2,
        A2, A2, Cch,
        nullptr, 0, nullptr, 0, 1);

    // 9) global softmax (scale = C^-0.5 = 1/16)
    softmax_rows<<<Bn * A2, 256>>>((float*)p_attg, A2, 1.f / 16.f);

    // 10) global output: hg[c,q] = sum_p vp[c,p] att[q,p]
    sgemm_kernel<false, true><<<dim3(cdiv(A2, 128), cdiv(Cch, 128), Bn), 256>>>(
        qkvp + 512LL * A2,   768LL * A2, A2,          // A = vp (MxK, lda=3136)
        (const float*)p_attg, (long long)A2 * A2, A2, // B = att (NxK -> transB)
        (float*)p_hg, (long long)Cch * A2, A2,
        Cch, A2, A2,
        nullptr, 0, nullptr, 0, 1);

    // 11) combine: 0.75*h_patch + 0.25*bilinear(hg)
    combine_kernel<<<16384, 256>>>((float*)p_h, (const float*)p_hp, (const float*)p_hg);

    // 12) projection + residual: out = x + Wproj @ h
    sgemm_kernel<false, false><<<dim3(cdiv(HW, 128), cdiv(Cch, 128), Bn), 256>>>(
        wproj, 0, 256,
        (const float*)p_h, (long long)Cch * HW, HW,
        out, (long long)Cch * HW, HW,
        Cch, HW, Cch,
        nullptr, 0,
        x, (long long)Cch * HW, 1);
}

// round 2
// speedup vs baseline: 2.1696x; 2.1696x over previous
#include <cuda_runtime.h>
#include <cuda_bf16.h>
#include <mma.h>
#include <math.h>
#include <type_traits>

using namespace nvcuda;

// ---------------------------------------------------------------------------
// Problem constants
// ---------------------------------------------------------------------------
namespace cfg {
constexpr int Bn  = 8;
constexpr int Cch = 256;
constexpr int Hh  = 112;
constexpr int Ww  = 112;
constexpr int HW  = Hh * Ww;        // 12544
constexpr int Pp  = 196;            // patch_area
constexpr int CS  = Cch * 64;       // 16384
constexpr int TG  = 56;             // target_global
constexpr int A2  = TG * TG;        // 3136
}
using namespace cfg;

// ---------------------------------------------------------------------------
// Scratch (__device__ globals)
// ---------------------------------------------------------------------------
__device__ __nv_bfloat16 g_xh   [(long long)Bn * Cch * HW];   // x in bf16
__device__ __nv_bfloat16 g_wph  [(long long)Bn * 768 * 256];  // folded qkv weights bf16
__device__ __nv_bfloat16 g_wprojh[256 * 256];
__device__ __nv_bfloat16 g_qkv  [(long long)Bn * 768 * HW];   // q/k/v slab bf16
__device__ __nv_bfloat16 g_qkvp [(long long)Bn * 768 * A2];   // pooled q/k/v bf16
__device__ float         g_attp [(long long)Bn * Pp * Pp];    // patch logits (fp32, split-K atomics)
__device__ __nv_bfloat16 g_attph[(long long)Bn * Pp * Pp];    // patch probs bf16
__device__ __nv_bfloat16 g_attg [(long long)Bn * A2 * A2];    // global logits/probs bf16 (157MB)
__device__ float         g_hp   [(long long)Bn * Cch * HW];   // patch attn out fp32
__device__ float         g_hg   [(long long)Bn * Cch * A2];   // global attn out fp32
__device__ __nv_bfloat16 g_h    [(long long)Bn * Cch * HW];   // combined h bf16
__device__ float         g_bp   [(long long)Bn * 768];        // folded biases fp32
__device__ double        g_stats[2 * Bn];
__device__ float         g_mu[Bn], g_rstd[Bn];

// ---------------------------------------------------------------------------
// GroupNorm statistics
// ---------------------------------------------------------------------------
__global__ void stats_kernel(const float* __restrict__ x)
{
    int b = blockIdx.y;
    const float* xb = x + (long long)b * Cch * HW;
    long long n = (long long)Cch * HW;
    double s = 0.0, s2 = 0.0;
    for (long long i = blockIdx.x * (long long)blockDim.x + threadIdx.x; i < n;
         i += (long long)gridDim.x * blockDim.x) {
        double v = xb[i];
        s += v; s2 += v * v;
    }
    __shared__ double rs[256], rs2[256];
    int tid = threadIdx.x;
    rs[tid] = s; rs2[tid] = s2;
    __syncthreads();
    for (int t = 128; t > 0; t >>= 1) {
        if (tid < t) { rs[tid] += rs[tid + t]; rs2[tid] += rs2[tid + t]; }
        __syncthreads();
    }
    if (tid == 0) {
        atomicAdd(&g_stats[2 * b],     rs[0]);
        atomicAdd(&g_stats[2 * b + 1], rs2[0]);
    }
}

__global__ void finalize_stats()
{
    int b = threadIdx.x;
    if (b < Bn) {
        double n    = (double)Cch * HW;
        double mean = g_stats[2 * b] / n;
        double var  = g_stats[2 * b + 1] / n - mean * mean;
        g_mu[b]   = (float)mean;
        g_rstd[b] = (float)(1.0 / sqrt(var + 1e-5));
    }
}

// ---------------------------------------------------------------------------
// Fold GroupNorm into QKV weights (bf16 out) + bias fold (fp32)
// ---------------------------------------------------------------------------
__global__ void prep_weights(const float* __restrict__ wq, const float* __restrict__ bq,
                             const float* __restrict__ wk, const float* __restrict__ bk,
                             const float* __restrict__ wv, const float* __restrict__ bv,
                             const float* __restrict__ gnw, const float* __restrict__ gnb)
{
    int r = blockIdx.x;            // 0..767
    int b = blockIdx.y;
    int mat = r >> 8, o = r & 255;
    const float* W  = (mat == 0) ? wq : (mat == 1) ? wk : wv;
    const float* bi = (mat == 0) ? bq : (mat == 1) ? bk : bv;
    int c = threadIdx.x;           // 256 threads
    float rstd = g_rstd[b], mu = g_mu[b];
    float w = W[o * 256 + c];
    g_wph[((long long)b * 768 + r) * 256 + c] = __float2bfloat16(w * gnw[c] * rstd);
    float contrib = w * (gnb[c] - gnw[c] * rstd * mu);
    __shared__ float red[256];
    red[c] = contrib;
    __syncthreads();
    for (int s = 128; s > 0; s >>= 1) {
        if (c < s) red[c] += red[c + s];
        __syncthreads();
    }
    if (c == 0) g_bp[(long long)b * 768 + r] = red[0] + bi[o];
}

// ---------------------------------------------------------------------------
// fp32 -> bf16 converters
// ---------------------------------------------------------------------------
__global__ void conv_x(const float* __restrict__ x, __nv_bfloat16* __restrict__ out, long long n)
{
    for (long long i = blockIdx.x * (long long)blockDim.x + threadIdx.x; i < n;
         i += (long long)gridDim.x * blockDim.x)
        out[i] = __float2bfloat16(x[i]);
}

// ---------------------------------------------------------------------------
// bf16 tensor-core GEMM: C[m,n] = alpha * sum_k opA(m,k)*opB(k,n) (+bias[m]) (+resid)
//   TA=false: A row-major [M,K];  TA=true: A is [K,M] (k-major)
//   TB=false: B row-major [K,N];  TB=true: B is [N,K] (n-major)
// Block tile 128x64x32, 8 warps (4 along M x 2 along N), 32x32 warp tile.
// fp32 accumulation; ksplit>1 -> fp32 atomicAdd (OutT must be float).
// ---------------------------------------------------------------------------
constexpr int BM = 128, BN = 64, BK = 32;
constexpr int LDA_R = BK + 8;   // 40 (row-major A smem, [BM][LDA_R])
constexpr int LDA_C = BM + 8;   // 136 (k-major A smem, [BK][LDA_C])
constexpr int LDB_R = BN + 8;   // 72 ([BK][LDB_R])
constexpr int LDB_C = BK + 8;   // 40 ([BN][LDB_C])
constexpr int LDC_S = BN + 4;   // 68

template <bool TA, bool TB, typename OutT>
__global__ void __launch_bounds__(256)
hgemm(const __nv_bfloat16* __restrict__ A, long long sA, int lda,
      const __nv_bfloat16* __restrict__ Bm, long long sB, int ldb,
      OutT* __restrict__ Cm, long long sC, int ldc,
      int M, int N, int K, float alpha,
      const float* __restrict__ bias, long long sBias,
      const float* __restrict__ resid, long long sRes,
      int ksplit)
{
    __shared__ __align__(128) char smem_raw[BM * LDC_S * 4];  // 34816 B (tiles alias this)
    __nv_bfloat16* As = (__nv_bfloat16*)smem_raw;
    __nv_bfloat16* Bs = (__nv_bfloat16*)(smem_raw + 10240);
    float*         Cs = (float*)smem_raw;

    int z = blockIdx.z;
    int batch = z / ksplit;
    int kc    = z - batch * ksplit;
    int kchunk = (K + ksplit - 1) / ksplit;
    int k0 = kc * kchunk;
    int kEnd = min(K, k0 + kchunk);

    const __nv_bfloat16* Ab = A  + (long long)batch * sA;
    const __nv_bfloat16* Bb = Bm + (long long)batch * sB;
    OutT*                Cb = Cm + (long long)batch * sC;

    int m0 = blockIdx.y * BM;
    int n0 = blockIdx.x * BN;

    int tid = threadIdx.x;
    int warp = tid >> 5;
    int wm = warp & 3;        // 0..3 along M
    int wn = warp >> 2;       // 0..1 along N

    using ALay = typename std::conditional<TA, wmma::col_major, wmma::row_major>::type;
    using BLay = typename std::conditional<TB, wmma::col_major, wmma::row_major>::type;
    wmma::fragment<wmma::accumulator, 16, 16, 16, float> acc[2][2];
#pragma unroll
    for (int i = 0; i < 2; i++)
#pragma unroll
        for (int j = 0; j < 2; j++) wmma::fill_fragment(acc[i][j], 0.f);

    for (int kk = k0; kk < kEnd; kk += BK) {
        // ---- A tile ----
        if (TA) {
            // As[k][m], k-major global
#pragma unroll
            for (int i = 0; i < 8; i++) {
                int lin = tid + i * 256;        // 0..2047
                int r  = lin >> 6;              // k 0..31
                int c2 = lin & 63;              // m pair
                int m = m0 + (c2 << 1);
                int k = kk + r;
                unsigned int val = 0;
                if (k < kEnd && m < M)
                    val = *(const unsigned int*)&Ab[(long long)k * lda + m];
                *(unsigned int*)&As[r * LDA_C + (c2 << 1)] = val;
            }
        } else {
            // As[m][k], row-major global
#pragma unroll
            for (int i = 0; i < 8; i++) {
                int lin = tid + i * 256;
                int r  = lin >> 4;              // m 0..127
                int c2 = lin & 15;              // k pair
                int m = m0 + r;
                int k = kk + (c2 << 1);
                unsigned int val = 0;
                if (m < M && k < kEnd)
                    val = *(const unsigned int*)&Ab[(long long)m * lda + k];
                *(unsigned int*)&As[r * LDA_R + (c2 << 1)] = val;
            }
        }
        // ---- B tile ----
        if (TB) {
            // Bs[n][k], n-major global
#pragma unroll
            for (int i = 0; i < 4; i++) {
                int lin = tid + i * 256;        // 0..1023
                int r  = lin >> 4;              // n 0..63
                int c2 = lin & 15;              // k pair
                int n = n0 + r;
                int k = kk + (c2 << 1);
                unsigned int val = 0;
                if (n < N && k < kEnd)
                    val = *(const unsigned int*)&Bb[(long long)n * ldb + k];
                *(unsigned int*)&Bs[r * LDB_C + (c2 << 1)] = val;
            }
        } else {
            // Bs[k][n]
#pragma unroll
            for (int i = 0; i < 4; i++) {
                int lin = tid + i * 256;
                int r  = lin >> 5;              // k 0..31
                int c2 = lin & 31;              // n pair
                int k = kk + r;
                int n = n0 + (c2 << 1);
                unsigned int val = 0;
                if (k < kEnd && n < N)
                    val = *(const unsigned int*)&Bb[(long long)k * ldb + n];
                *(unsigned int*)&Bs[r * LDB_R + (c2 << 1)] = val;
            }
        }
        __syncthreads();

#pragma unroll
        for (int ks = 0; ks < 2; ks++) {
            int kof = ks * 16;
            wmma::fragment<wmma::matrix_a, 16, 16, 16, __nv_bfloat16, ALay> a[2];
            wmma::fragment<wmma::matrix_b, 16, 16, 16, __nv_bfloat16, BLay> b[2];
#pragma unroll
            for (int i = 0; i < 2; i++) {
                int mf = wm * 32 + i * 16;
                if (TA) wmma::load_matrix_sync(a[i], &As[kof * LDA_C + mf], LDA_C);
                else    wmma::load_matrix_sync(a[i], &As[mf * LDA_R + kof], LDA_R);
            }
#pragma unroll
            for (int j = 0; j < 2; j++) {
                int nf = wn * 32 + j * 16;
                if (TB) wmma::load_matrix_sync(b[j], &Bs[nf * LDB_C + kof], LDB_C);
                else    wmma::load_matrix_sync(b[j], &Bs[kof * LDB_R + nf], LDB_R);
            }
#pragma unroll
            for (int i = 0; i < 2; i++)
#pragma unroll
                for (int j = 0; j < 2; j++)
                    wmma::mma_sync(acc[i][j], a[i], b[j], acc[i][j]);
        }
        __syncthreads();
    }

    // ---- epilogue through smem ----
#pragma unroll
    for (int i = 0; i < 2; i++)
#pragma unroll
        for (int j = 0; j < 2; j++)
            wmma::store_matrix_sync(&Cs[(wm * 32 + i * 16) * LDC_S + wn * 32 + j * 16],
                                    acc[i][j], LDC_S, wmma::mem_row_major);
    __syncthreads();

#pragma unroll
    for (int t = 0; t < 32; t++) {
        int lin = tid + t * 256;
        int mi = lin >> 6;        // 0..127
        int ni = lin & 63;
        int m = m0 + mi, n = n0 + ni;
        if (m < M && n < N) {
            float v = Cs[mi * LDC_S + ni] * alpha;
            if (bias)  v += bias[batch * sBias + m];
            long long idx = (long long)m * ldc + n;
            if (resid) v += resid[batch * sRes + idx];
            if (ksplit > 1) {
                if constexpr (std::is_same<OutT, float>::value) atomicAdd(&Cb[idx], v);
            } else {
                if constexpr (std::is_same<OutT, float>::value) Cb[idx] = v;
                else Cb[idx] = __float2bfloat16(v);
            }
        }
    }
}

// ---------------------------------------------------------------------------
// 2x2 average pool (bf16 -> bf16)
// ---------------------------------------------------------------------------
__global__ void pool_kernel(const __nv_bfloat16* __restrict__ qkv, __nv_bfloat16* __restrict__ out)
{
    long long total = (long long)Bn * 768 * A2;
    for (long long idx = blockIdx.x * (long long)blockDim.x + threadIdx.x; idx < total;
         idx += (long long)gridDim.x * blockDim.x) {
        int p = (int)(idx % A2);
        long long br = idx / A2;
        int y = p / TG, x = p % TG;
        const __nv_bfloat16* src = qkv + br * HW;
        float v = __bfloat162float(src[(2 * y) * Ww + 2 * x])
                + __bfloat162float(src[(2 * y) * Ww + 2 * x + 1])
                + __bfloat162float(src[(2 * y + 1) * Ww + 2 * x])
                + __bfloat162float(src[(2 * y + 1) * Ww + 2 * x + 1]);
        out[idx] = __float2bfloat16(0.25f * v);
    }
}

// ---------------------------------------------------------------------------
// Patch softmax: fp32 logits in (scale already applied), bf16 probs out. len=196
// ---------------------------------------------------------------------------
__global__ void softmax_patch(const float* __restrict__ in, __nv_bfloat16* __restrict__ out)
{
    long long row = blockIdx.x;
    const float* p = in  + row * Pp;
    __nv_bfloat16* q = out + row * Pp;
    __shared__ float red[256];
    int tid = threadIdx.x;
    float v = (tid < Pp) ? p[tid] : -1e30f;
    red[tid] = v;
    __syncthreads();
    for (int s = 128; s > 0; s >>= 1) {
        if (tid < s) red[tid] = fmaxf(red[tid], red[tid + s]);
        __syncthreads();
    }
    float m = red[0];
    __syncthreads();
    float e = (tid < Pp) ? __expf(v - m) : 0.f;
    red[tid] = e;
    __syncthreads();
    for (int s = 128; s > 0; s >>= 1) {
        if (tid < s) red[tid] += red[tid + s];
        __syncthreads();
    }
    float inv = 1.f / red[0];
    if (tid < Pp) q[tid] = __float2bfloat16(e * inv);
}

// ---------------------------------------------------------------------------
// Global softmax: bf16 in-place, len=3136, one exp per element
// ---------------------------------------------------------------------------
__global__ void softmax_global(__nv_bfloat16* __restrict__ data)
{
    long long row = blockIdx.x;
    __nv_bfloat16* p = data + row * A2;
    __shared__ float red[256];
    int tid = threadIdx.x;

    float v[13];
#pragma unroll
    for (int t = 0; t < 13; t++) {
        int i = tid + t * 256;
        v[t] = (i < A2) ? __bfloat162float(p[i]) : -1e30f;
    }
    float m = -1e30f;
#pragma unroll
    for (int t = 0; t < 13; t++) m = fmaxf(m, v[t]);
    red[tid] = m;
    __syncthreads();
    for (int s = 128; s > 0; s >>= 1) {
        if (tid < s) red[tid] = fmaxf(red[tid], red[tid + s]);
        __syncthreads();
    }
    m = red[0];
    __syncthreads();

    float sum = 0.f;
#pragma unroll
    for (int t = 0; t < 13; t++) {
        v[t] = __expf(v[t] - m);      // -1e30 -> 0
        sum += v[t];
    }
    red[tid] = sum;
    __syncthreads();
    for (int s = 128; s > 0; s >>= 1) {
        if (tid < s) red[tid] += red[tid + s];
        __syncthreads();
    }
    float inv = 1.f / red[0];
#pragma unroll
    for (int t = 0; t < 13; t++) {
        int i = tid + t * 256;
        if (i < A2) p[i] = __float2bfloat16(v[t] * inv);
    }
}

// ---------------------------------------------------------------------------
// Combine: h = 0.75*hp + 0.25*bilinear(hg 56->112); bf16 out
// ---------------------------------------------------------------------------
__global__ void combine_kernel(__nv_bfloat16* __restrict__ h,
                               const float* __restrict__ hp,
                               const float* __restrict__ hg)
{
    long long total = (long long)Bn * Cch * HW;
    for (long long idx = blockIdx.x * (long long)blockDim.x + threadIdx.x; idx < total;
         idx += (long long)gridDim.x * blockDim.x) {
        int hw = (int)(idx % HW);
        long long bc = idx / HW;
        int i = hw / Ww, j = hw % Ww;
        float sy = 0.5f * i - 0.25f;
        float sx = 0.5f * j - 0.25f;
        int y0 = (int)floorf(sy), x0 = (int)floorf(sx);
        float wy = sy - (float)y0, wx = sx - (float)x0;
        int y0c = min(max(y0, 0), TG - 1), y1c = min(max(y0 + 1, 0), TG - 1);
        int x0c = min(max(x0, 0), TG - 1), x1c = min(max(x0 + 1, 0), TG - 1);
        const float* g = hg + bc * A2;
        float v00 = g[y0c * TG + x0c], v01 = g[y0c * TG + x1c];
        float v10 = g[y1c * TG + x0c], v11 = g[y1c * TG + x1c];
        float gv = (1.f - wy) * ((1.f - wx) * v00 + wx * v01)
                 +        wy  * ((1.f - wx) * v10 + wx * v11);
        h[idx] = __float2bfloat16(0.75f * hp[idx] + 0.25f * gv);
    }
}

// ---------------------------------------------------------------------------
// Launch
// ---------------------------------------------------------------------------
static inline int cdiv(int a, int b) { return (a + b - 1) / b; }

extern "C" void kernel_launch(void* const* d_in, const int* in_sizes, int n_in,
                              void* d_out, int out_size)
{
    const float* x     = (const float*)d_in[0];
    const float* gnw   = (const float*)d_in[1];
    const float* gnb   = (const float*)d_in[2];
    const float* wq    = (const float*)d_in[3];
    const float* bq    = (const float*)d_in[4];
    const float* wk    = (const float*)d_in[5];
    const float* bk    = (const float*)d_in[6];
    const float* wv    = (const float*)d_in[7];
    const float* bv    = (const float*)d_in[8];
    const float* wproj = (const float*)d_in[9];
    float* out = (float*)d_out;

    void *p_xh, *p_wph, *p_wprojh, *p_qkv, *p_qkvp, *p_attp, *p_attph, *p_attg,
         *p_hp, *p_hg, *p_h, *p_bp, *p_stats;
    cudaGetSymbolAddress(&p_xh,    g_xh);
    cudaGetSymbolAddress(&p_wph,   g_wph);
    cudaGetSymbolAddress(&p_wprojh,g_wprojh);
    cudaGetSymbolAddress(&p_qkv,   g_qkv);
    cudaGetSymbolAddress(&p_qkvp,  g_qkvp);
    cudaGetSymbolAddress(&p_attp,  g_attp);
    cudaGetSymbolAddress(&p_attph, g_attph);
    cudaGetSymbolAddress(&p_attg,  g_attg);
    cudaGetSymbolAddress(&p_hp,    g_hp);
    cudaGetSymbolAddress(&p_hg,    g_hg);
    cudaGetSymbolAddress(&p_h,     g_h);
    cudaGetSymbolAddress(&p_bp,    g_bp);
    cudaGetSymbolAddress(&p_stats, g_stats);

    const __nv_bfloat16* xh   = (const __nv_bfloat16*)p_xh;
    const __nv_bfloat16* qkv  = (const __nv_bfloat16*)p_qkv;
    const __nv_bfloat16* qkvp = (const __nv_bfloat16*)p_qkvp;

    // 1) GroupNorm stats
    cudaMemsetAsync(p_stats, 0, 2 * Bn * sizeof(double));
    stats_kernel<<<dim3(128, Bn), 256>>>(x);
    finalize_stats<<<1, Bn>>>();

    // 2) weight prep + conversions
    prep_weights<<<dim3(768, Bn), 256>>>(wq, bq, wk, bk, wv, bv, gnw, gnb);
    conv_x<<<4096, 256>>>(x, (__nv_bfloat16*)p_xh, (long long)Bn * Cch * HW);
    conv_x<<<64, 256>>>(wproj, (__nv_bfloat16*)p_wprojh, 256 * 256);

    // 3) QKV GEMM (bias), bf16 out
    hgemm<false, false, __nv_bfloat16><<<dim3(cdiv(HW, BN), cdiv(768, BM), Bn), 256>>>(
        (const __nv_bfloat16*)p_wph, 768LL * 256, 256,
        xh, (long long)Cch * HW, HW,
        (__nv_bfloat16*)p_qkv, 768LL * HW, HW,
        768, HW, 256, 1.f,
        (const float*)p_bp, 768, nullptr, 0, 1);

    // 4) 2x2 average pool
    pool_kernel<<<8192, 256>>>(qkv, (__nv_bfloat16*)p_qkvp);

    // 5) patch logits: alpha = (C*S)^-0.5 = 1/128, split-K=32
    cudaMemsetAsync(p_attp, 0, (long long)Bn * Pp * Pp * sizeof(float));
    hgemm<true, false, float><<<dim3(cdiv(Pp, BN), cdiv(Pp, BM), Bn * 32), 256>>>(
        qkv,              768LL * HW, Pp,
        qkv + 256LL * HW, 768LL * HW, Pp,
        (float*)p_attp, (long long)Pp * Pp, Pp,
        Pp, Pp, CS, 1.f / 128.f,
        nullptr, 0, nullptr, 0, 32);

    // 6) patch softmax -> bf16 probs
    softmax_patch<<<Bn * Pp, 256>>>((const float*)p_attp, (__nv_bfloat16*)p_attph);

    // 7) patch out: hp[d,q] = sum_p v[d,p] att[q,p]
    hgemm<false, true, float><<<dim3(cdiv(Pp, BN), cdiv(CS, BM), Bn), 256>>>(
        qkv + 512LL * HW, 768LL * HW, Pp,
        (const __nv_bfloat16*)p_attph, (long long)Pp * Pp, Pp,
        (float*)p_hp, (long long)Cch * HW, Pp,
        CS, Pp, Pp, 1.f,
        nullptr, 0, nullptr, 0, 1);

    // 8) global logits: alpha = C^-0.5 = 1/16, bf16 out
    hgemm<true, false, __nv_bfloat16><<<dim3(cdiv(A2, BN), cdiv(A2, BM), Bn), 256>>>(
        qkvp,              768LL * A2, A2,
        qkvp + 256LL * A2, 768LL * A2, A2,
        (__nv_bfloat16*)p_attg, (long long)A2 * A2, A2,
        A2, A2, Cch, 1.f / 16.f,
        nullptr, 0, nullptr, 0, 1);

    // 9) global softmax (in-place bf16)
    softmax_global<<<Bn * A2, 256>>>((__nv_bfloat16*)p_attg);

    // 10) global out: hg[c,q] = sum_p vp[c,p] att[q,p], split-K=2
    cudaMemsetAsync(p_hg, 0, (long long)Bn * Cch * A2 * sizeof(float));
    hgemm<false, true, float><<<dim3(cdiv(A2, BN), cdiv(Cch, BM), Bn * 2), 256>>>(
        qkvp + 512LL * A2, 768LL * A2, A2,
        (const __nv_bfloat16*)p_attg, (long long)A2 * A2, A2,
        (float*)p_hg, (long long)Cch * A2, A2,
        Cch, A2, A2, 1.f,
        nullptr, 0, nullptr, 0, 2);

    // 11) combine -> bf16 h
    combine_kernel<<<16384, 256>>>((__nv_bfloat16*)p_h, (const float*)p_hp, (const float*)p_hg);

    // 12) proj + residual (fp32 out)
    hgemm<false, false, float><<<dim3(cdiv(HW, BN), cdiv(Cch, BM), Bn), 256>>>(
        (const __nv_bfloat16*)p_wprojh, 0, 256,
        (const __nv_bfloat16*)p_h, (long long)Cch * HW, HW,
        out, (long long)Cch * HW, HW,
        Cch, HW, 256, 1.f,
        nullptr, 0,
        x, (long long)Cch * HW, 1);
}